// round 6
// baseline (speedup 1.0000x reference)
#include <cuda_runtime.h>
#include <cstdint>

#define H1 10
#define H2 19
#define TPB 256
#define EPT 2            // edges per thread (packed f32x2)
#define EPB (TPB * EPT)  // 512 edges per block

// ---------------- packed f32x2 helpers (sm_103a) ----------------
__device__ __forceinline__ unsigned long long pack2(float lo, float hi) {
    unsigned long long r;
    asm("mov.b64 %0, {%1, %2};" : "=l"(r) : "f"(lo), "f"(hi));
    return r;
}
__device__ __forceinline__ void unpack2(unsigned long long v, float& lo, float& hi) {
    asm("mov.b64 {%0, %1}, %2;" : "=f"(lo), "=f"(hi) : "l"(v));
}
__device__ __forceinline__ unsigned long long fma2(unsigned long long a,
                                                   unsigned long long b,
                                                   unsigned long long c) {
    unsigned long long d;
    asm("fma.rn.f32x2 %0, %1, %2, %3;" : "=l"(d) : "l"(a), "l"(b), "l"(c));
    return d;
}

__global__ __launch_bounds__(TPB)
void edge_mlp_kernel(const float* __restrict__ src,
                     const float* __restrict__ dst_,
                     const float* __restrict__ ea,
                     const float* __restrict__ u,
                     const int* __restrict__ batch,     // int32 (JAX x64 disabled)
                     const float* __restrict__ W1,
                     const float* __restrict__ b1,
                     const float* __restrict__ W2,
                     const float* __restrict__ b2,
                     float* __restrict__ out,
                     long long E)
{
    // weights duplicated into both f32x2 lanes
    __shared__ unsigned long long sW1[4 * H1];   // 40
    __shared__ unsigned long long sB1[H1];       // 10
    __shared__ unsigned long long sW2[H1 * H2];  // 190
    __shared__ unsigned long long sB2[H2];       // 19
    __shared__ __align__(16) float sOut[EPB * H2];  // 512*19 = 9728 floats

    const int t = threadIdx.x;

    // ---- stage weights (duplicated into both lanes for packed math) ----
    for (int i = t; i < 40 + 10 + 190 + 19; i += TPB) {
        float w;
        unsigned long long* d;
        if (i < 40)        { w = W1[i];        d = &sW1[i]; }
        else if (i < 50)   { w = b1[i - 40];   d = &sB1[i - 40]; }
        else if (i < 240)  { w = W2[i - 50];   d = &sW2[i - 50]; }
        else               { w = b2[i - 240];  d = &sB2[i - 240]; }
        *d = pack2(w, w);
    }
    __syncthreads();

    const long long base = (long long)blockIdx.x * EPB;
    const long long e0 = base + 2 * t;   // this thread's adjacent edge pair
    const bool full_block = (base + EPB) <= E;

    if (e0 + 1 < E) {
        // ---- load the pair of edges (all 64-bit coalesced loads) ----
        float2 s2 = *reinterpret_cast<const float2*>(src  + e0);
        float2 d2 = *reinterpret_cast<const float2*>(dst_ + e0);
        float2 a2 = *reinterpret_cast<const float2*>(ea   + e0);
        int2   g2 = *reinterpret_cast<const int2*>(batch + e0);
        float u0 = __ldg(u + g2.x);
        float u1 = __ldg(u + g2.y);

        unsigned long long xs = pack2(s2.x, s2.y);
        unsigned long long xd = pack2(d2.x, d2.y);
        unsigned long long xa = pack2(a2.x, a2.y);
        unsigned long long xu = pack2(u0, u1);

        // ---- layer 1: 4 -> 10, ReLU ----
        unsigned long long h[H1];
        #pragma unroll
        for (int j = 0; j < H1; j++) {
            unsigned long long acc = sB1[j];
            acc = fma2(xs, sW1[0 * H1 + j], acc);
            acc = fma2(xd, sW1[1 * H1 + j], acc);
            acc = fma2(xa, sW1[2 * H1 + j], acc);
            acc = fma2(xu, sW1[3 * H1 + j], acc);
            float lo, hi;
            unpack2(acc, lo, hi);
            h[j] = pack2(fmaxf(lo, 0.0f), fmaxf(hi, 0.0f));
        }

        // ---- layer 2: 10 -> 19, stage into smem ----
        float* row0 = &sOut[(2 * t) * H2];
        float* row1 = row0 + H2;
        #pragma unroll
        for (int c = 0; c < H2; c++) {
            unsigned long long acc = sB2[c];
            #pragma unroll
            for (int j = 0; j < H1; j++)
                acc = fma2(h[j], sW2[j * H2 + c], acc);
            float lo, hi;
            unpack2(acc, lo, hi);
            row0[c] = lo;
            row1[c] = hi;
        }
    } else if (e0 < E) {
        // scalar tail (single remaining edge)
        float xs = src[e0], xd = dst_[e0], xa = ea[e0];
        float xu = __ldg(u + batch[e0]);
        float hs[H1];
        #pragma unroll
        for (int j = 0; j < H1; j++) {
            float lo, hi, dummy;
            unpack2(sB1[j], lo, dummy);
            float w0, w1, w2, w3;
            unpack2(sW1[0 * H1 + j], w0, dummy);
            unpack2(sW1[1 * H1 + j], w1, dummy);
            unpack2(sW1[2 * H1 + j], w2, dummy);
            unpack2(sW1[3 * H1 + j], w3, dummy);
            hi = lo + xs * w0 + xd * w1 + xa * w2 + xu * w3;
            hs[j] = fmaxf(hi, 0.0f);
        }
        float* row0 = &sOut[(2 * t) * H2];
        #pragma unroll
        for (int c = 0; c < H2; c++) {
            float acc, dummy;
            unpack2(sB2[c], acc, dummy);
            #pragma unroll
            for (int j = 0; j < H1; j++) {
                float w;
                unpack2(sW2[j * H2 + c], w, dummy);
                acc += hs[j] * w;
            }
            row0[c] = acc;
        }
    }
    __syncthreads();

    // ---- coalesced writeback ----
    if (full_block) {
        // base*H2*4 bytes = blockIdx*38912 bytes, 16B-aligned -> float4 path
        float4* og = reinterpret_cast<float4*>(out + base * H2);
        const float4* so = reinterpret_cast<const float4*>(sOut);
        #pragma unroll 4
        for (int i = t; i < (EPB * H2) / 4; i += TPB)
            og[i] = so[i];
    } else {
        long long nfl = (E - base) * H2;  // floats remaining
        for (long long i = t; i < nfl; i += TPB)
            out[base * H2 + i] = sOut[i];
    }
}

extern "C" void kernel_launch(void* const* d_in, const int* in_sizes, int n_in,
                              void* d_out, int out_size) {
    const float* src   = (const float*)d_in[0];
    const float* dest  = (const float*)d_in[1];
    const float* ea    = (const float*)d_in[2];
    const float* u     = (const float*)d_in[3];
    const int*   batch = (const int*)d_in[4];
    const float* W1    = (const float*)d_in[5];
    const float* b1    = (const float*)d_in[6];
    const float* W2    = (const float*)d_in[7];
    const float* b2    = (const float*)d_in[8];
    float* out = (float*)d_out;

    long long E = in_sizes[0];  // src has E elements ([E,1])
    int grid = (int)((E + EPB - 1) / EPB);
    edge_mlp_kernel<<<grid, TPB>>>(src, dest, ea, u, batch, W1, b1, W2, b2, out, E);
}

// round 14
// speedup vs baseline: 1.3900x; 1.3900x over previous
#include <cuda_runtime.h>
#include <cstdint>

#define H1 10
#define H2 19
#define TPB 256
#define EPT 2            // edges per thread (packed f32x2)
#define EPB (TPB * EPT)  // 512 edges per block
#define MAX_B 4096       // u staged in SMEM when n_graphs <= MAX_B

// ---------------- packed f32x2 helpers (sm_103a) ----------------
__device__ __forceinline__ unsigned long long pack2(float lo, float hi) {
    unsigned long long r;
    asm("mov.b64 %0, {%1, %2};" : "=l"(r) : "f"(lo), "f"(hi));
    return r;
}
__device__ __forceinline__ void unpack2(unsigned long long v, float& lo, float& hi) {
    asm("mov.b64 {%0, %1}, %2;" : "=f"(lo), "=f"(hi) : "l"(v));
}
__device__ __forceinline__ unsigned long long fma2(unsigned long long a,
                                                   unsigned long long b,
                                                   unsigned long long c) {
    unsigned long long d;
    asm("fma.rn.f32x2 %0, %1, %2, %3;" : "=l"(d) : "l"(a), "l"(b), "l"(c));
    return d;
}
__device__ __forceinline__ uint32_t smem_u32(const void* p) {
    uint32_t a;
    asm("{ .reg .u64 t; cvta.to.shared.u64 t, %1; cvt.u32.u64 %0, t; }"
        : "=r"(a) : "l"(p));
    return a;
}

__global__ __launch_bounds__(TPB)
void edge_mlp_kernel(const float* __restrict__ src,
                     const float* __restrict__ dst_,
                     const float* __restrict__ ea,
                     const float* __restrict__ u,
                     const int* __restrict__ batch,     // int32
                     const float* __restrict__ W1,
                     const float* __restrict__ b1,
                     const float* __restrict__ W2,
                     const float* __restrict__ b2,
                     float* __restrict__ out,
                     long long E, int nB)
{
    __shared__ unsigned long long sW1[4 * H1];   // duplicated lanes
    __shared__ unsigned long long sB1[H1];
    __shared__ unsigned long long sW2[H1 * H2];
    __shared__ unsigned long long sB2[H2];
    __shared__ __align__(16) float sU[MAX_B];        // 16 KB staged u (16B-aligned!)
    __shared__ __align__(16) float sOut[EPB * H2];   // 38912 B output tile

    const int t = threadIdx.x;
    const bool stageU = (nB <= MAX_B);

    // ---- stage weights ----
    for (int i = t; i < 40 + 10 + 190 + 19; i += TPB) {
        float w;
        unsigned long long* d;
        if (i < 40)        { w = W1[i];        d = &sW1[i]; }
        else if (i < 50)   { w = b1[i - 40];   d = &sB1[i - 40]; }
        else if (i < 240)  { w = W2[i - 50];   d = &sW2[i - 50]; }
        else               { w = b2[i - 240];  d = &sB2[i - 240]; }
        *d = pack2(w, w);
    }
    // ---- stage u (coalesced; L2-resident source) ----
    if (stageU) {
        if ((nB & 3) == 0) {
            const float4* u4 = reinterpret_cast<const float4*>(u);
            float4* s4 = reinterpret_cast<float4*>(sU);
            for (int i = t; i < (nB >> 2); i += TPB) s4[i] = u4[i];
        } else {
            for (int i = t; i < nB; i += TPB) sU[i] = u[i];
        }
    }
    __syncthreads();

    const long long base = (long long)blockIdx.x * EPB;
    const long long e0 = base + 2 * t;
    const bool full_block = (base + EPB) <= E;

    if (e0 + 1 < E) {
        float2 s2 = *reinterpret_cast<const float2*>(src  + e0);
        float2 d2 = *reinterpret_cast<const float2*>(dst_ + e0);
        float2 a2 = *reinterpret_cast<const float2*>(ea   + e0);
        int2   g2 = *reinterpret_cast<const int2*>(batch + e0);
        float u0, u1;
        if (stageU) { u0 = sU[g2.x]; u1 = sU[g2.y]; }
        else        { u0 = __ldg(u + g2.x); u1 = __ldg(u + g2.y); }

        unsigned long long xs = pack2(s2.x, s2.y);
        unsigned long long xd = pack2(d2.x, d2.y);
        unsigned long long xa = pack2(a2.x, a2.y);
        unsigned long long xu = pack2(u0, u1);

        // ---- layer 1: 4 -> 10, ReLU (packed over the edge pair) ----
        unsigned long long h[H1];
        #pragma unroll
        for (int j = 0; j < H1; j++) {
            unsigned long long acc = sB1[j];
            acc = fma2(xs, sW1[0 * H1 + j], acc);
            acc = fma2(xd, sW1[1 * H1 + j], acc);
            acc = fma2(xa, sW1[2 * H1 + j], acc);
            acc = fma2(xu, sW1[3 * H1 + j], acc);
            float lo, hi;
            unpack2(acc, lo, hi);
            h[j] = pack2(fmaxf(lo, 0.0f), fmaxf(hi, 0.0f));
        }

        // ---- layer 2: 10 -> 19 ----
        // lo lane -> row0 via aligned STS.64 pairs; hi lane kept in regs,
        // then row1 stored with the odd-start pairing that matches its
        // 4-mod-8 base offset.
        float hiArr[H2];
        float* row0 = &sOut[(2 * t) * H2];          // byte off 152t (0 mod 8)
        float* row1 = row0 + H2;                    // byte off 152t+76 (4 mod 8)
        #pragma unroll
        for (int c = 0; c < H2 - 1; c += 2) {
            unsigned long long acc0 = sB2[c];
            unsigned long long acc1 = sB2[c + 1];
            #pragma unroll
            for (int j = 0; j < H1; j++) {
                acc0 = fma2(h[j], sW2[j * H2 + c], acc0);
                acc1 = fma2(h[j], sW2[j * H2 + c + 1], acc1);
            }
            float l0, h0, l1, h1;
            unpack2(acc0, l0, h0);
            unpack2(acc1, l1, h1);
            *reinterpret_cast<unsigned long long*>(row0 + c) = pack2(l0, l1); // 8B-aligned
            hiArr[c] = h0;
            hiArr[c + 1] = h1;
        }
        {   // last channel (c = 18)
            const int c = H2 - 1;
            unsigned long long acc = sB2[c];
            #pragma unroll
            for (int j = 0; j < H1; j++)
                acc = fma2(h[j], sW2[j * H2 + c], acc);
            float lo, hi;
            unpack2(acc, lo, hi);
            row0[c] = lo;
            hiArr[c] = hi;
        }
        row1[0] = hiArr[0];                          // scalar (4-mod-8 base)
        #pragma unroll
        for (int c = 1; c < H2 - 1; c += 2)          // (1,2)(3,4)...(17,18)
            *reinterpret_cast<unsigned long long*>(row1 + c) =
                pack2(hiArr[c], hiArr[c + 1]);       // 76+4c, c odd -> 8B-aligned
    } else if (e0 < E) {
        // scalar tail (single remaining edge)
        float xs = src[e0], xd = dst_[e0], xa = ea[e0];
        int g = batch[e0];
        float xu = stageU ? sU[g] : __ldg(u + g);
        float hs[H1];
        #pragma unroll
        for (int j = 0; j < H1; j++) {
            float lo, dummy;
            unpack2(sB1[j], lo, dummy);
            float w0, w1, w2, w3;
            unpack2(sW1[0 * H1 + j], w0, dummy);
            unpack2(sW1[1 * H1 + j], w1, dummy);
            unpack2(sW1[2 * H1 + j], w2, dummy);
            unpack2(sW1[3 * H1 + j], w3, dummy);
            hs[j] = fmaxf(lo + xs * w0 + xd * w1 + xa * w2 + xu * w3, 0.0f);
        }
        float* row0 = &sOut[(2 * t) * H2];
        #pragma unroll
        for (int c = 0; c < H2; c++) {
            float acc, dummy;
            unpack2(sB2[c], acc, dummy);
            #pragma unroll
            for (int j = 0; j < H1; j++) {
                float w;
                unpack2(sW2[j * H2 + c], w, dummy);
                acc += hs[j] * w;
            }
            row0[c] = acc;
        }
    }
    __syncthreads();

    // ---- async bulk writeback: SMEM tile -> GMEM via bulk-copy engine ----
    if (full_block) {
        if (t == 0) {
            asm volatile("fence.proxy.async.shared::cta;" ::: "memory");
            uint32_t s = smem_u32(sOut);
            float* g = out + base * H2;   // byte addr = 38912*blockIdx (16B mult)
            asm volatile(
                "cp.async.bulk.global.shared::cta.bulk_group [%0], [%1], %2;"
                :: "l"(g), "r"(s), "r"((uint32_t)(EPB * H2 * 4)) : "memory");
            asm volatile("cp.async.bulk.commit_group;" ::: "memory");
            asm volatile("cp.async.bulk.wait_group 0;" ::: "memory");
        }
    } else {
        long long nfl = (E - base) * H2;  // floats remaining
        for (long long i = t; i < nfl; i += TPB)
            out[base * H2 + i] = sOut[i];
    }
}

extern "C" void kernel_launch(void* const* d_in, const int* in_sizes, int n_in,
                              void* d_out, int out_size) {
    const float* src   = (const float*)d_in[0];
    const float* dest  = (const float*)d_in[1];
    const float* ea    = (const float*)d_in[2];
    const float* u     = (const float*)d_in[3];
    const int*   batch = (const int*)d_in[4];
    const float* W1    = (const float*)d_in[5];
    const float* b1    = (const float*)d_in[6];
    const float* W2    = (const float*)d_in[7];
    const float* b2    = (const float*)d_in[8];
    float* out = (float*)d_out;

    long long E = in_sizes[0];
    int nB = in_sizes[3];
    int grid = (int)((E + EPB - 1) / EPB);
    edge_mlp_kernel<<<grid, TPB>>>(src, dest, ea, u, batch, W1, b1, W2, b2,
                                   out, E, nB);
}

// round 15
// speedup vs baseline: 1.6805x; 1.2090x over previous
#include <cuda_runtime.h>
#include <cstdint>

#define H1 10
#define H2 19
#define TPB 256
#define EPT 2            // edges per thread (packed f32x2)
#define EPB (TPB * EPT)  // 512 edges per block
#define MAX_B 4096       // u staged in SMEM when n_graphs <= MAX_B

// ---------------- packed f32x2 helpers (sm_103a) ----------------
__device__ __forceinline__ unsigned long long pack2(float lo, float hi) {
    unsigned long long r;
    asm("mov.b64 %0, {%1, %2};" : "=l"(r) : "f"(lo), "f"(hi));
    return r;
}
__device__ __forceinline__ void unpack2(unsigned long long v, float& lo, float& hi) {
    asm("mov.b64 {%0, %1}, %2;" : "=f"(lo), "=f"(hi) : "l"(v));
}
__device__ __forceinline__ unsigned long long fma2(unsigned long long a,
                                                   unsigned long long b,
                                                   unsigned long long c) {
    unsigned long long d;
    asm("fma.rn.f32x2 %0, %1, %2, %3;" : "=l"(d) : "l"(a), "l"(b), "l"(c));
    return d;
}
__device__ __forceinline__ uint32_t smem_u32(const void* p) {
    uint32_t a;
    asm("{ .reg .u64 t; cvta.to.shared.u64 t, %1; cvt.u32.u64 %0, t; }"
        : "=r"(a) : "l"(p));
    return a;
}

__global__ __launch_bounds__(TPB, 4)
void edge_mlp_kernel(const float* __restrict__ src,
                     const float* __restrict__ dst_,
                     const float* __restrict__ ea,
                     const float* __restrict__ u,
                     const int* __restrict__ batch,     // int32
                     const float* __restrict__ W1,
                     const float* __restrict__ b1,
                     const float* __restrict__ W2,
                     const float* __restrict__ b2,
                     float* __restrict__ out,
                     long long E, int nB)
{
    __shared__ unsigned long long sW1[4 * H1];   // duplicated lanes
    __shared__ unsigned long long sB1[H1];
    __shared__ unsigned long long sW2[H1 * H2];
    __shared__ unsigned long long sB2[H2];
    __shared__ __align__(16) float sU[MAX_B];        // 16 KB staged u
    __shared__ __align__(16) float sOut[EPB * H2];   // 38912 B output tile

    const int t = threadIdx.x;
    const bool stageU = (nB <= MAX_B);

    // ---- stage weights ----
    for (int i = t; i < 40 + 10 + 190 + 19; i += TPB) {
        float w;
        unsigned long long* d;
        if (i < 40)        { w = W1[i];        d = &sW1[i]; }
        else if (i < 50)   { w = b1[i - 40];   d = &sB1[i - 40]; }
        else if (i < 240)  { w = W2[i - 50];   d = &sW2[i - 50]; }
        else               { w = b2[i - 240];  d = &sB2[i - 240]; }
        *d = pack2(w, w);
    }
    // ---- stage u (coalesced; L2-resident source) ----
    if (stageU) {
        if ((nB & 3) == 0) {
            const float4* u4 = reinterpret_cast<const float4*>(u);
            float4* s4 = reinterpret_cast<float4*>(sU);
            for (int i = t; i < (nB >> 2); i += TPB) s4[i] = u4[i];
        } else {
            for (int i = t; i < nB; i += TPB) sU[i] = u[i];
        }
    }
    __syncthreads();

    const long long base = (long long)blockIdx.x * EPB;
    const long long e0 = base + 2 * t;
    const bool full_block = (base + EPB) <= E;

    if (e0 + 1 < E) {
        float2 s2 = *reinterpret_cast<const float2*>(src  + e0);
        float2 d2 = *reinterpret_cast<const float2*>(dst_ + e0);
        float2 a2 = *reinterpret_cast<const float2*>(ea   + e0);
        int2   g2 = *reinterpret_cast<const int2*>(batch + e0);
        float u0, u1;
        if (stageU) { u0 = sU[g2.x]; u1 = sU[g2.y]; }
        else        { u0 = __ldg(u + g2.x); u1 = __ldg(u + g2.y); }

        unsigned long long xs = pack2(s2.x, s2.y);
        unsigned long long xd = pack2(d2.x, d2.y);
        unsigned long long xa = pack2(a2.x, a2.y);
        unsigned long long xu = pack2(u0, u1);

        // ---- layer 1: 4 -> 10, ReLU (packed over the edge pair) ----
        unsigned long long h[H1];
        #pragma unroll
        for (int j = 0; j < H1; j++) {
            unsigned long long acc = sB1[j];
            acc = fma2(xs, sW1[0 * H1 + j], acc);
            acc = fma2(xd, sW1[1 * H1 + j], acc);
            acc = fma2(xa, sW1[2 * H1 + j], acc);
            acc = fma2(xu, sW1[3 * H1 + j], acc);
            float lo, hi;
            unpack2(acc, lo, hi);
            h[j] = pack2(fmaxf(lo, 0.0f), fmaxf(hi, 0.0f));
        }

        // ---- layer 2: 10 -> 19 ----
        // row0 (lo lane, base 152t: 0 mod 8): even-pair STS.64 as we go.
        // row1 (hi lane, base 152t+76: 4 mod 8): odd-pair STS.64 via a
        // single carry register — store pack(carry, h_c) at row1+(c-1)
        // (byte 152t+72+4c, c even -> 0 mod 8). No 19-float array.
        float* row0 = &sOut[(2 * t) * H2];
        float* row1 = row0 + H2;
        float carry = 0.0f;
        #pragma unroll
        for (int c = 0; c < H2 - 1; c += 2) {
            unsigned long long acc0 = sB2[c];
            unsigned long long acc1 = sB2[c + 1];
            #pragma unroll
            for (int j = 0; j < H1; j++) {
                acc0 = fma2(h[j], sW2[j * H2 + c], acc0);
                acc1 = fma2(h[j], sW2[j * H2 + c + 1], acc1);
            }
            float l0, h0, l1, h1;
            unpack2(acc0, l0, h0);
            unpack2(acc1, l1, h1);
            *reinterpret_cast<unsigned long long*>(row0 + c) = pack2(l0, l1);
            if (c == 0) {
                row1[0] = h0;                 // scalar (4-mod-8 base)
            } else {
                *reinterpret_cast<unsigned long long*>(row1 + (c - 1)) =
                    pack2(carry, h0);         // aligned odd-pair
            }
            carry = h1;
        }
        {   // last channel (c = 18)
            const int c = H2 - 1;
            unsigned long long acc = sB2[c];
            #pragma unroll
            for (int j = 0; j < H1; j++)
                acc = fma2(h[j], sW2[j * H2 + c], acc);
            float lo, hi;
            unpack2(acc, lo, hi);
            row0[c] = lo;
            *reinterpret_cast<unsigned long long*>(row1 + (c - 1)) =
                pack2(carry, hi);             // (17,18): byte 152t+144, aligned
        }
    } else if (e0 < E) {
        // scalar tail (single remaining edge)
        float xs = src[e0], xd = dst_[e0], xa = ea[e0];
        int g = batch[e0];
        float xu = stageU ? sU[g] : __ldg(u + g);
        float hs[H1];
        #pragma unroll
        for (int j = 0; j < H1; j++) {
            float lo, dummy;
            unpack2(sB1[j], lo, dummy);
            float w0, w1, w2, w3;
            unpack2(sW1[0 * H1 + j], w0, dummy);
            unpack2(sW1[1 * H1 + j], w1, dummy);
            unpack2(sW1[2 * H1 + j], w2, dummy);
            unpack2(sW1[3 * H1 + j], w3, dummy);
            hs[j] = fmaxf(lo + xs * w0 + xd * w1 + xa * w2 + xu * w3, 0.0f);
        }
        float* row0 = &sOut[(2 * t) * H2];
        #pragma unroll
        for (int c = 0; c < H2; c++) {
            float acc, dummy;
            unpack2(sB2[c], acc, dummy);
            #pragma unroll
            for (int j = 0; j < H1; j++) {
                float w;
                unpack2(sW2[j * H2 + c], w, dummy);
                acc += hs[j] * w;
            }
            row0[c] = acc;
        }
    }
    __syncthreads();

    // ---- async bulk writeback: SMEM tile -> GMEM via bulk-copy engine ----
    if (full_block) {
        if (t == 0) {
            asm volatile("fence.proxy.async.shared::cta;" ::: "memory");
            uint32_t s = smem_u32(sOut);
            float* g = out + base * H2;   // byte addr = 38912*blockIdx (16B mult)
            asm volatile(
                "cp.async.bulk.global.shared::cta.bulk_group [%0], [%1], %2;"
                :: "l"(g), "r"(s), "r"((uint32_t)(EPB * H2 * 4)) : "memory");
            asm volatile("cp.async.bulk.commit_group;" ::: "memory");
            asm volatile("cp.async.bulk.wait_group 0;" ::: "memory");
        }
    } else {
        long long nfl = (E - base) * H2;  // floats remaining
        for (long long i = t; i < nfl; i += TPB)
            out[base * H2 + i] = sOut[i];
    }
}

extern "C" void kernel_launch(void* const* d_in, const int* in_sizes, int n_in,
                              void* d_out, int out_size) {
    const float* src   = (const float*)d_in[0];
    const float* dest  = (const float*)d_in[1];
    const float* ea    = (const float*)d_in[2];
    const float* u     = (const float*)d_in[3];
    const int*   batch = (const int*)d_in[4];
    const float* W1    = (const float*)d_in[5];
    const float* b1    = (const float*)d_in[6];
    const float* W2    = (const float*)d_in[7];
    const float* b2    = (const float*)d_in[8];
    float* out = (float*)d_out;

    long long E = in_sizes[0];
    int nB = in_sizes[3];
    int grid = (int)((E + EPB - 1) / EPB);
    edge_mlp_kernel<<<grid, TPB>>>(src, dest, ea, u, batch, W1, b1, W2, b2,
                                   out, E, nB);
}

// round 16
// speedup vs baseline: 1.8427x; 1.0965x over previous
#include <cuda_runtime.h>
#include <cstdint>

#define H1 10
#define H2 19
#define TPB 256
#define EPT 2            // edges per thread (packed f32x2)
#define EPB (TPB * EPT)  // 512 edges per tile
#define MAX_B 4096       // u staged in SMEM when n_graphs <= MAX_B
#define NCTA 444         // persistent grid: 3 CTAs x 148 SMs

// ---------------- packed f32x2 helpers (sm_103a) ----------------
__device__ __forceinline__ unsigned long long pack2(float lo, float hi) {
    unsigned long long r;
    asm("mov.b64 %0, {%1, %2};" : "=l"(r) : "f"(lo), "f"(hi));
    return r;
}
__device__ __forceinline__ void unpack2(unsigned long long v, float& lo, float& hi) {
    asm("mov.b64 {%0, %1}, %2;" : "=f"(lo), "=f"(hi) : "l"(v));
}
__device__ __forceinline__ unsigned long long fma2(unsigned long long a,
                                                   unsigned long long b,
                                                   unsigned long long c) {
    unsigned long long d;
    asm("fma.rn.f32x2 %0, %1, %2, %3;" : "=l"(d) : "l"(a), "l"(b), "l"(c));
    return d;
}
__device__ __forceinline__ uint32_t smem_u32(const void* p) {
    uint32_t a;
    asm("{ .reg .u64 t; cvta.to.shared.u64 t, %1; cvt.u32.u64 %0, t; }"
        : "=r"(a) : "l"(p));
    return a;
}

__global__ __launch_bounds__(TPB, 3)
void edge_mlp_kernel(const float* __restrict__ src,
                     const float* __restrict__ dst_,
                     const float* __restrict__ ea,
                     const float* __restrict__ u,
                     const int* __restrict__ batch,     // int32
                     const float* __restrict__ W1,
                     const float* __restrict__ b1,
                     const float* __restrict__ W2,
                     const float* __restrict__ b2,
                     float* __restrict__ out,
                     long long E, int nB)
{
    __shared__ unsigned long long sW1[4 * H1];   // duplicated lanes
    __shared__ unsigned long long sB1[H1];
    __shared__ unsigned long long sW2[H1 * H2];
    __shared__ unsigned long long sB2[H2];
    __shared__ __align__(16) float sU[MAX_B];        // 16 KB staged u
    __shared__ __align__(16) float sOut[EPB * H2];   // 38912 B output tile

    const int t = threadIdx.x;
    const bool stageU = (nB <= MAX_B);

    // ---- stage weights (ONCE per persistent CTA) ----
    for (int i = t; i < 40 + 10 + 190 + 19; i += TPB) {
        float w;
        unsigned long long* d;
        if (i < 40)        { w = W1[i];        d = &sW1[i]; }
        else if (i < 50)   { w = b1[i - 40];   d = &sB1[i - 40]; }
        else if (i < 240)  { w = W2[i - 50];   d = &sW2[i - 50]; }
        else               { w = b2[i - 240];  d = &sB2[i - 240]; }
        *d = pack2(w, w);
    }
    // ---- stage u (ONCE per persistent CTA) ----
    if (stageU) {
        if ((nB & 3) == 0) {
            const float4* u4 = reinterpret_cast<const float4*>(u);
            float4* s4 = reinterpret_cast<float4*>(sU);
            for (int i = t; i < (nB >> 2); i += TPB) s4[i] = u4[i];
        } else {
            for (int i = t; i < nB; i += TPB) sU[i] = u[i];
        }
    }
    __syncthreads();

    const long long ntiles = (E + EPB - 1) / EPB;

    for (long long tile = blockIdx.x; tile < ntiles; tile += gridDim.x) {
        const long long base = tile * EPB;
        const long long e0 = base + 2 * t;
        const bool full_block = (base + EPB) <= E;
        const bool pair_ok = (e0 + 1 < E);

        // ======== front work: overlaps the PREVIOUS tile's bulk-copy drain ====
        unsigned long long h[H1];
        if (pair_ok) {
            float2 s2 = *reinterpret_cast<const float2*>(src  + e0);
            float2 d2 = *reinterpret_cast<const float2*>(dst_ + e0);
            float2 a2 = *reinterpret_cast<const float2*>(ea   + e0);
            int2   g2 = *reinterpret_cast<const int2*>(batch + e0);
            float u0, u1;
            if (stageU) { u0 = sU[g2.x]; u1 = sU[g2.y]; }
            else        { u0 = __ldg(u + g2.x); u1 = __ldg(u + g2.y); }

            unsigned long long xs = pack2(s2.x, s2.y);
            unsigned long long xd = pack2(d2.x, d2.y);
            unsigned long long xa = pack2(a2.x, a2.y);
            unsigned long long xu = pack2(u0, u1);

            // layer 1: 4 -> 10, ReLU (packed over the edge pair)
            #pragma unroll
            for (int j = 0; j < H1; j++) {
                unsigned long long acc = sB1[j];
                acc = fma2(xs, sW1[0 * H1 + j], acc);
                acc = fma2(xd, sW1[1 * H1 + j], acc);
                acc = fma2(xa, sW1[2 * H1 + j], acc);
                acc = fma2(xu, sW1[3 * H1 + j], acc);
                float lo, hi;
                unpack2(acc, lo, hi);
                h[j] = pack2(fmaxf(lo, 0.0f), fmaxf(hi, 0.0f));
            }
        }

        // ======== release sOut: previous tile's TMA must have READ it =========
        __syncthreads();                       // everyone finished front work
        if (t == 0)
            asm volatile("cp.async.bulk.wait_group.read 0;" ::: "memory");
        __syncthreads();                       // sOut safe to overwrite

        // ======== layer 2: 10 -> 19, stage into sOut ==========================
        if (pair_ok) {
            // row0 (lo lane, base 152t: 0 mod 8): even-pair STS.64.
            // row1 (hi lane, base 152t+76: 4 mod 8): scalar c=0, then odd-pair
            // STS.64 via 1-register carry (byte 152t+72+4c, c even -> 0 mod 8).
            float* row0 = &sOut[(2 * t) * H2];
            float* row1 = row0 + H2;
            float carry = 0.0f;
            #pragma unroll
            for (int c = 0; c < H2 - 1; c += 2) {
                unsigned long long acc0 = sB2[c];
                unsigned long long acc1 = sB2[c + 1];
                #pragma unroll
                for (int j = 0; j < H1; j++) {
                    acc0 = fma2(h[j], sW2[j * H2 + c], acc0);
                    acc1 = fma2(h[j], sW2[j * H2 + c + 1], acc1);
                }
                float l0, h0, l1, h1;
                unpack2(acc0, l0, h0);
                unpack2(acc1, l1, h1);
                *reinterpret_cast<unsigned long long*>(row0 + c) = pack2(l0, l1);
                if (c == 0) {
                    row1[0] = h0;
                } else {
                    *reinterpret_cast<unsigned long long*>(row1 + (c - 1)) =
                        pack2(carry, h0);
                }
                carry = h1;
            }
            {   // last channel (c = 18)
                const int c = H2 - 1;
                unsigned long long acc = sB2[c];
                #pragma unroll
                for (int j = 0; j < H1; j++)
                    acc = fma2(h[j], sW2[j * H2 + c], acc);
                float lo, hi;
                unpack2(acc, lo, hi);
                row0[c] = lo;
                *reinterpret_cast<unsigned long long*>(row1 + (c - 1)) =
                    pack2(carry, hi);
            }
        } else if (e0 < E) {
            // scalar tail (single remaining edge)
            float xs = src[e0], xd = dst_[e0], xa = ea[e0];
            int g = batch[e0];
            float xu = stageU ? sU[g] : __ldg(u + g);
            float hs[H1];
            #pragma unroll
            for (int j = 0; j < H1; j++) {
                float lo, dummy;
                unpack2(sB1[j], lo, dummy);
                float w0, w1, w2, w3;
                unpack2(sW1[0 * H1 + j], w0, dummy);
                unpack2(sW1[1 * H1 + j], w1, dummy);
                unpack2(sW1[2 * H1 + j], w2, dummy);
                unpack2(sW1[3 * H1 + j], w3, dummy);
                hs[j] = fmaxf(lo + xs * w0 + xd * w1 + xa * w2 + xu * w3, 0.0f);
            }
            float* row0 = &sOut[(2 * t) * H2];
            #pragma unroll
            for (int c = 0; c < H2; c++) {
                float acc, dummy;
                unpack2(sB2[c], acc, dummy);
                #pragma unroll
                for (int j = 0; j < H1; j++) {
                    float w;
                    unpack2(sW2[j * H2 + c], w, dummy);
                    acc += hs[j] * w;
                }
                row0[c] = acc;
            }
        }
        __syncthreads();                       // STS visible to async proxy

        // ======== kick off async writeback; do NOT wait here ==================
        if (full_block) {
            if (t == 0) {
                asm volatile("fence.proxy.async.shared::cta;" ::: "memory");
                uint32_t s = smem_u32(sOut);
                float* g = out + base * H2;   // 38912*tile bytes, 16B multiple
                asm volatile(
                    "cp.async.bulk.global.shared::cta.bulk_group [%0], [%1], %2;"
                    :: "l"(g), "r"(s), "r"((uint32_t)(EPB * H2 * 4)) : "memory");
                asm volatile("cp.async.bulk.commit_group;" ::: "memory");
            }
        } else {
            long long nfl = (E - base) * H2;  // floats remaining
            for (long long i = t; i < nfl; i += TPB)
                out[base * H2 + i] = sOut[i];
        }
        // loop: next iteration's LDG/layer-1 overlap this drain
    }

    // ---- final drain before CTA exit ----
    __syncthreads();
    if (t == 0)
        asm volatile("cp.async.bulk.wait_group 0;" ::: "memory");
    __syncthreads();
}

extern "C" void kernel_launch(void* const* d_in, const int* in_sizes, int n_in,
                              void* d_out, int out_size) {
    const float* src   = (const float*)d_in[0];
    const float* dest  = (const float*)d_in[1];
    const float* ea    = (const float*)d_in[2];
    const float* u     = (const float*)d_in[3];
    const int*   batch = (const int*)d_in[4];
    const float* W1    = (const float*)d_in[5];
    const float* b1    = (const float*)d_in[6];
    const float* W2    = (const float*)d_in[7];
    const float* b2    = (const float*)d_in[8];
    float* out = (float*)d_out;

    long long E = in_sizes[0];
    int nB = in_sizes[3];
    long long ntiles = (E + EPB - 1) / EPB;
    int grid = (int)(ntiles < NCTA ? ntiles : NCTA);
    edge_mlp_kernel<<<grid, TPB>>>(src, dest, ea, u, batch, W1, b1, W2, b2,
                                   out, E, nB);
}